// round 13
// baseline (speedup 1.0000x reference)
#include <cuda_runtime.h>
#include <math.h>

#define NN 100000
#define NE 3200000
#define EBLK ((NE + 255) / 256)
#define NBLK ((NN + 255) / 256)

// ---------------- scratch ---------------------------------------------------
__device__ float g_tmp[NN * 8];
__device__ float g_aggA[NN * 8];
__device__ float g_aggB[NN * 8];
__device__ int2  g_edge[NE];
__device__ int   g_is64;

// ---------------- f32x2 helpers --------------------------------------------
__device__ __forceinline__ unsigned long long bcast2(float x) {
    unsigned long long r;
    unsigned u = __float_as_uint(x);
    asm("mov.b64 %0, {%1, %1};" : "=l"(r) : "r"(u));
    return r;
}
__device__ __forceinline__ void ffma2(unsigned long long& d,
                                      unsigned long long a, unsigned long long b) {
    asm("fma.rn.f32x2 %0, %1, %2, %0;" : "+l"(d) : "l"(a), "l"(b));
}
__device__ __forceinline__ void unpack2(unsigned long long v, float& lo, float& hi) {
    asm("mov.b64 {%0, %1}, %2;" : "=f"(lo), "=f"(hi) : "l"(v));
}

// ---------------- 128-bit vector reduction (sm_90+) ------------------------
__device__ __forceinline__ void red4(float* p, float a, float b, float c, float d) {
    asm volatile("red.global.add.v4.f32 [%0], {%1,%2,%3,%4};"
                 :: "l"(p), "f"(a), "f"(b), "f"(c), "f"(d) : "memory");
}

// ---------------- detect int64 vs int32 edge_index -------------------------
__global__ void detect_kernel(const unsigned int* __restrict__ w) {
    unsigned v = w[threadIdx.x * 2 + 1];
    int any = __syncthreads_or(v != 0u);
    if (threadIdx.x == 0) g_is64 = any ? 0 : 1;
}

// ---------------- zero one agg buffer ---------------------------------------
__global__ void zero_buf(float* buf) {
    int i = blockIdx.x * blockDim.x + threadIdx.x;
    if (i < NN * 2) ((float4*)buf)[i] = make_float4(0.f, 0.f, 0.f, 0.f);
}

// ---------------- layer-1: g_tmp = x @ W1 (512 -> 8) -----------------------
// 8-lane groups, 4 nodes/group. Lane (c = r&3, rh = r>>2) owns k = i*16+c*4+t
// and outputs [4rh, 4rh+4). acc = 4 nodes x 2 f32x2 = 16 regs.
// Shared W granules: gid = i*32 + t*8 + c*2 + rh, 16B = W1[k*8 + 4rh .. +3]
// -> each LDS.128 hits 8 distinct bank-groups, broadcast across groups.
__global__ void __launch_bounds__(256, 4) l1_kernel(const float* __restrict__ x,
                                                    const float* __restrict__ W1) {
    __shared__ __align__(16) ulonglong2 shw[1024];   // 16 KB
    const int tid = threadIdx.x;

    // stage: contiguous 16B chunks of row-major W1
    for (int gid = tid; gid < 1024; gid += 256) {
        int kb = gid >> 5, rem = gid & 31;
        int t = rem >> 3, c = (rem >> 1) & 3, rh = rem & 1;
        int k = kb * 16 + c * 4 + t;
        float4 v = __ldg((const float4*)(W1 + k * 8 + 4 * rh));
        shw[gid] = *(const ulonglong2*)&v;
    }
    __syncthreads();

    const int lane = tid & 31;
    const int warp = tid >> 5;
    const int g  = lane >> 3;
    const int r  = lane & 7;
    const int c  = r & 3;
    const int rh = r >> 2;

    int nb = blockIdx.x * 128 + warp * 16 + g * 4;
    nb = min(nb, NN - 4);                 // clamp: duplicate groups recompute
    const float* xbase = x + (size_t)nb * 512 + c * 4;
    const ulonglong2* wbase = shw + (c * 2 + rh);

    unsigned long long acc[4][2];
#pragma unroll
    for (int j = 0; j < 4; j++) { acc[j][0] = 0ull; acc[j][1] = 0ull; }

#pragma unroll 2
    for (int i = 0; i < 32; i++) {
        const float* xk = xbase + i * 16;
        float4 v0 = __ldg((const float4*)(xk));
        float4 v1 = __ldg((const float4*)(xk + 512));
        float4 v2 = __ldg((const float4*)(xk + 1024));
        float4 v3 = __ldg((const float4*)(xk + 1536));
        const ulonglong2* wt = wbase + i * 32;
        ulonglong2 w0 = wt[0];
        ulonglong2 w1 = wt[8];
        ulonglong2 w2 = wt[16];
        ulonglong2 w3 = wt[24];

        unsigned long long xb;
        // t = 0
        xb = bcast2(v0.x); ffma2(acc[0][0], xb, w0.x); ffma2(acc[0][1], xb, w0.y);
        xb = bcast2(v1.x); ffma2(acc[1][0], xb, w0.x); ffma2(acc[1][1], xb, w0.y);
        xb = bcast2(v2.x); ffma2(acc[2][0], xb, w0.x); ffma2(acc[2][1], xb, w0.y);
        xb = bcast2(v3.x); ffma2(acc[3][0], xb, w0.x); ffma2(acc[3][1], xb, w0.y);
        // t = 1
        xb = bcast2(v0.y); ffma2(acc[0][0], xb, w1.x); ffma2(acc[0][1], xb, w1.y);
        xb = bcast2(v1.y); ffma2(acc[1][0], xb, w1.x); ffma2(acc[1][1], xb, w1.y);
        xb = bcast2(v2.y); ffma2(acc[2][0], xb, w1.x); ffma2(acc[2][1], xb, w1.y);
        xb = bcast2(v3.y); ffma2(acc[3][0], xb, w1.x); ffma2(acc[3][1], xb, w1.y);
        // t = 2
        xb = bcast2(v0.z); ffma2(acc[0][0], xb, w2.x); ffma2(acc[0][1], xb, w2.y);
        xb = bcast2(v1.z); ffma2(acc[1][0], xb, w2.x); ffma2(acc[1][1], xb, w2.y);
        xb = bcast2(v2.z); ffma2(acc[2][0], xb, w2.x); ffma2(acc[2][1], xb, w2.y);
        xb = bcast2(v3.z); ffma2(acc[3][0], xb, w2.x); ffma2(acc[3][1], xb, w2.y);
        // t = 3
        xb = bcast2(v0.w); ffma2(acc[0][0], xb, w3.x); ffma2(acc[0][1], xb, w3.y);
        xb = bcast2(v1.w); ffma2(acc[1][0], xb, w3.x); ffma2(acc[1][1], xb, w3.y);
        xb = bcast2(v2.w); ffma2(acc[2][0], xb, w3.x); ffma2(acc[2][1], xb, w3.y);
        xb = bcast2(v3.w); ffma2(acc[3][0], xb, w3.x); ffma2(acc[3][1], xb, w3.y);
    }

    // reduce over c (XOR 1,2 keeps rh fixed); lane c==0 writes float4 #rh
#pragma unroll
    for (int j = 0; j < 4; j++) {
        float s[4];
        unpack2(acc[j][0], s[0], s[1]);
        unpack2(acc[j][1], s[2], s[3]);
#pragma unroll
        for (int d = 1; d < 4; d <<= 1) {
#pragma unroll
            for (int o = 0; o < 4; o++)
                s[o] += __shfl_xor_sync(0xffffffffu, s[o], d);
        }
        if (c == 0) {
            float4* tp = (float4*)(g_tmp + (size_t)(nb + j) * 8 + 4 * rh);
            *tp = make_float4(s[0], s[1], s[2], s[3]);
        }
    }
}

// ---------------- edge pass 1: fused convert + scatter (tmp -> aggA) -------
__global__ void edgecv_k(const void* __restrict__ edge_index,
                         const float* __restrict__ w) {
    int e = blockIdx.x * blockDim.x + threadIdx.x;
    if (e >= NE) return;
    int s, d;
    if (g_is64) {
        const long long* p = (const long long*)edge_index;
        s = (int)__ldg(&p[e]); d = (int)__ldg(&p[NE + e]);
    } else {
        const int* p = (const int*)edge_index;
        s = __ldg(&p[e]); d = __ldg(&p[NE + e]);
    }
    g_edge[e] = make_int2(s, d);
    float wt = __ldg(&w[e]);
    const float4* ts = (const float4*)(g_tmp + (size_t)s * 8);
    float* ad = g_aggA + (size_t)d * 8;
    float4 a = __ldg(ts);
    float4 b = __ldg(ts + 1);
    red4(ad,     a.x * wt, a.y * wt, a.z * wt, a.w * wt);
    red4(ad + 4, b.x * wt, b.y * wt, b.z * wt, b.w * wt);
}

// ---------------- edge pass: plain (tmp -> aggA) ---------------------------
__global__ void edge_k(const float* __restrict__ w) {
    int e = blockIdx.x * blockDim.x + threadIdx.x;
    if (e >= NE) return;
    int2 sd = __ldg(&g_edge[e]);
    float wt = __ldg(&w[e]);
    const float4* ts = (const float4*)(g_tmp + (size_t)sd.x * 8);
    float* ad = g_aggA + (size_t)sd.y * 8;
    float4 a = __ldg(ts);
    float4 b = __ldg(ts + 1);
    red4(ad,     a.x * wt, a.y * wt, a.z * wt, a.w * wt);
    red4(ad + 4, b.x * wt, b.y * wt, b.z * wt, b.w * wt);
}

// ---------------- edge pass with fused relu: relu(aggA[src]+b)*w -> aggB ---
__global__ void edge_relu_k(const float* __restrict__ w,
                            const float* __restrict__ bias) {
    int e = blockIdx.x * blockDim.x + threadIdx.x;
    if (e >= NE) return;
    int2 sd = __ldg(&g_edge[e]);
    float wt = __ldg(&w[e]);
    const float4* ts = (const float4*)(g_aggA + (size_t)sd.x * 8);
    float* ad = g_aggB + (size_t)sd.y * 8;
    float4 a = __ldg(ts);
    float4 b = __ldg(ts + 1);
    float h0 = fmaxf(a.x + __ldg(&bias[0]), 0.f);
    float h1 = fmaxf(a.y + __ldg(&bias[1]), 0.f);
    float h2 = fmaxf(a.z + __ldg(&bias[2]), 0.f);
    float h3 = fmaxf(a.w + __ldg(&bias[3]), 0.f);
    float h4 = fmaxf(b.x + __ldg(&bias[4]), 0.f);
    float h5 = fmaxf(b.y + __ldg(&bias[5]), 0.f);
    float h6 = fmaxf(b.z + __ldg(&bias[6]), 0.f);
    float h7 = fmaxf(b.w + __ldg(&bias[7]), 0.f);
    red4(ad,     h0 * wt, h1 * wt, h2 * wt, h3 * wt);
    red4(ad + 4, h4 * wt, h5 * wt, h6 * wt, h7 * wt);
}

// ---------------- fused mid: tmp = relu(aggB@W2 + b2) @ W3; zero aggA,aggB -
__global__ void tmid(const float* __restrict__ W2, const float* __restrict__ b2,
                     const float* __restrict__ W3) {
    int n = blockIdx.x * blockDim.x + threadIdx.x;
    if (n >= NN) return;
    float4* brow = (float4*)(g_aggB + (size_t)n * 8);
    float4 v0 = brow[0], v1 = brow[1];
    float h[8] = {v0.x, v0.y, v0.z, v0.w, v1.x, v1.y, v1.z, v1.w};
    float4 z = make_float4(0.f, 0.f, 0.f, 0.f);
    brow[0] = z; brow[1] = z;
    float4* arow = (float4*)(g_aggA + (size_t)n * 8);
    arow[0] = z; arow[1] = z;

    float m[16];
#pragma unroll
    for (int o = 0; o < 16; o++) m[o] = __ldg(&b2[o]);
#pragma unroll
    for (int j = 0; j < 8; j++) {
        float hj = h[j];
#pragma unroll
        for (int o = 0; o < 16; o++)
            m[o] += hj * __ldg(&W2[j * 16 + o]);
    }
#pragma unroll
    for (int o = 0; o < 16; o++) m[o] = fmaxf(m[o], 0.f);

    float acc[8];
#pragma unroll
    for (int o = 0; o < 8; o++) acc[o] = 0.f;
#pragma unroll
    for (int j = 0; j < 16; j++) {
        float mj = m[j];
#pragma unroll
        for (int o = 0; o < 8; o++)
            acc[o] += mj * __ldg(&W3[j * 8 + o]);
    }
    float4* trow = (float4*)(g_tmp + (size_t)n * 8);
    trow[0] = make_float4(acc[0], acc[1], acc[2], acc[3]);
    trow[1] = make_float4(acc[4], acc[5], acc[6], acc[7]);
}

// ---------------- final: out = log_softmax(aggB@W4 + b4) -------------------
__global__ void lsm_kernel(const float* __restrict__ W4, const float* __restrict__ b4,
                           float* __restrict__ out) {
    int n = blockIdx.x * blockDim.x + threadIdx.x;
    if (n >= NN) return;
    const float4* brow = (const float4*)(g_aggB + (size_t)n * 8);
    float4 v0 = __ldg(brow), v1 = __ldg(brow + 1);
    float h[8] = {v0.x, v0.y, v0.z, v0.w, v1.x, v1.y, v1.z, v1.w};

    float v[10];
#pragma unroll
    for (int o = 0; o < 10; o++) v[o] = __ldg(&b4[o]);
#pragma unroll
    for (int j = 0; j < 8; j++) {
        float hj = h[j];
#pragma unroll
        for (int o = 0; o < 10; o++)
            v[o] += hj * __ldg(&W4[j * 10 + o]);
    }
    float m = -1e30f;
#pragma unroll
    for (int o = 0; o < 10; o++) m = fmaxf(m, v[o]);
    float s = 0.f;
#pragma unroll
    for (int o = 0; o < 10; o++) s += expf(v[o] - m);
    float l = logf(s);
#pragma unroll
    for (int o = 0; o < 10; o++) out[(size_t)n * 10 + o] = v[o] - m - l;
}

// ---------------- launch ---------------------------------------------------
extern "C" void kernel_launch(void* const* d_in, const int* in_sizes, int n_in,
                              void* d_out, int out_size) {
    const float* x  = (const float*)d_in[0];
    const void*  ei = d_in[1];
    const float* ew = (const float*)d_in[2];
    const float* W1 = (const float*)d_in[3];
    const float* b1 = (const float*)d_in[4];
    const float* W2 = (const float*)d_in[5];
    const float* b2 = (const float*)d_in[6];
    const float* W3 = (const float*)d_in[7];
    const float* b3 = (const float*)d_in[8];
    const float* W4 = (const float*)d_in[9];
    const float* b4 = (const float*)d_in[10];
    float* out = (float*)d_out;

    float* aggA; cudaGetSymbolAddress((void**)&aggA, g_aggA);
    float* aggB; cudaGetSymbolAddress((void**)&aggB, g_aggB);

    const int ZBLK = (NN * 2 + 255) / 256;
    detect_kernel<<<1, 256>>>((const unsigned int*)ei);      // 0
    zero_buf<<<ZBLK, 256>>>(aggA);                           // 1
    zero_buf<<<ZBLK, 256>>>(aggB);                           // 2
    l1_kernel<<<(NN + 127) / 128, 256>>>(x, W1);             // 3 (profiled)
    edgecv_k<<<EBLK, 256>>>(ei, ew);                         // 4: aggA = A@(xW1)

    edge_relu_k<<<EBLK, 256>>>(ew, b1);                      // aggB = A@relu(aggA+b1)
    tmid<<<NBLK, 256>>>(W2, b2, W3);                         // tmp = relu(aggB W2+b2)W3; aggA=aggB=0
    edge_k<<<EBLK, 256>>>(ew);                               // aggA = A@tmp
    edge_relu_k<<<EBLK, 256>>>(ew, b3);                      // aggB = A@relu(aggA+b3)
    lsm_kernel<<<NBLK, 256>>>(W4, b4, out);                  // out = lsm(aggB W4+b4)
}

// round 17
// speedup vs baseline: 1.0223x; 1.0223x over previous
#include <cuda_runtime.h>
#include <math.h>

#define NN 100000
#define NE 3200000
#define EBLK ((NE + 255) / 256)
#define NBLK ((NN + 255) / 256)

// ---------------- scratch ---------------------------------------------------
__device__ float g_tmp[NN * 8];
__device__ float g_aggA[NN * 8];
__device__ float g_aggB[NN * 8];
__device__ int2  g_edge[NE];
__device__ int   g_is64;

// ---------------- f32x2 helpers --------------------------------------------
__device__ __forceinline__ unsigned long long bcast2(float x) {
    unsigned long long r;
    unsigned u = __float_as_uint(x);
    asm("mov.b64 %0, {%1, %1};" : "=l"(r) : "r"(u));
    return r;
}
__device__ __forceinline__ void ffma2(unsigned long long& d,
                                      unsigned long long a, unsigned long long b) {
    asm("fma.rn.f32x2 %0, %1, %2, %0;" : "+l"(d) : "l"(a), "l"(b));
}
__device__ __forceinline__ void unpack2(unsigned long long v, float& lo, float& hi) {
    asm("mov.b64 {%0, %1}, %2;" : "=f"(lo), "=f"(hi) : "l"(v));
}

// ---------------- 128-bit vector reduction (sm_90+) ------------------------
__device__ __forceinline__ void red4(float* p, float a, float b, float c, float d) {
    asm volatile("red.global.add.v4.f32 [%0], {%1,%2,%3,%4};"
                 :: "l"(p), "f"(a), "f"(b), "f"(c), "f"(d) : "memory");
}

// ---------------- detect int64 vs int32 edge_index -------------------------
__global__ void detect_kernel(const unsigned int* __restrict__ w) {
    unsigned v = w[threadIdx.x * 2 + 1];
    int any = __syncthreads_or(v != 0u);
    if (threadIdx.x == 0) g_is64 = any ? 0 : 1;
}

// ---------------- layer-1: g_tmp = x @ W1 (512 -> 8); zero aggA/aggB -------
// R12 mainloop (best measured). 8-lane groups, 4 nodes/group, W1 in shared
// (transposed f32-pairs, XOR-granule swizzle), p-loop split in halves.
// Epilogue additionally zeroes this thread's float4 of aggA and aggB.
__global__ void __launch_bounds__(256, 3) l1_kernel(const float* __restrict__ x,
                                                    const float* __restrict__ W1) {
    __shared__ __align__(16) unsigned long long sh2[2048];   // 16 KB
    const int tid = threadIdx.x;

    // stage: byte addr = i*1024 + r*128 + ((p*2+which) ^ r)*16
#pragma unroll
    for (int s = tid; s < 1024; s += 256) {
        int i  = s >> 6;
        int r  = (s >> 3) & 7;
        int gp = s & 7;
        int pw = gp ^ r;
        int p = pw >> 1, which = pw & 1;
        int k0 = i * 32 + r * 4 + which * 2;
        unsigned a0 = __float_as_uint(__ldg(&W1[k0 * 8 + 2 * p]));
        unsigned a1 = __float_as_uint(__ldg(&W1[k0 * 8 + 2 * p + 1]));
        unsigned b0 = __float_as_uint(__ldg(&W1[(k0 + 1) * 8 + 2 * p]));
        unsigned b1 = __float_as_uint(__ldg(&W1[(k0 + 1) * 8 + 2 * p + 1]));
        unsigned long long lo, hi;
        asm("mov.b64 %0, {%1, %2};" : "=l"(lo) : "r"(a0), "r"(a1));
        asm("mov.b64 %0, {%1, %2};" : "=l"(hi) : "r"(b0), "r"(b1));
        *(ulonglong2*)((char*)sh2 + s * 16) = make_ulonglong2(lo, hi);
    }
    __syncthreads();

    const int lane = tid & 31;
    const int warp = tid >> 5;
    const int g = lane >> 3;
    const int r = lane & 7;

    const int nbase = blockIdx.x * 128 + warp * 16 + g * 4;
    const float* xr0 = x + (size_t)min(nbase + 0, NN - 1) * 512;
    const float* xr1 = x + (size_t)min(nbase + 1, NN - 1) * 512;
    const float* xr2 = x + (size_t)min(nbase + 2, NN - 1) * 512;
    const float* xr3 = x + (size_t)min(nbase + 3, NN - 1) * 512;

    const char* shb = (const char*)sh2 + r * 128;

    unsigned long long acc[4][4];   // [node][p]
#pragma unroll
    for (int j = 0; j < 4; j++)
#pragma unroll
        for (int p = 0; p < 4; p++) acc[j][p] = 0ull;

#pragma unroll 2
    for (int i = 0; i < 16; i++) {
        int kbase = i * 32 + r * 4;
        float4 v[4];
        v[0] = __ldg((const float4*)(xr0 + kbase));
        v[1] = __ldg((const float4*)(xr1 + kbase));
        v[2] = __ldg((const float4*)(xr2 + kbase));
        v[3] = __ldg((const float4*)(xr3 + kbase));

        const char* row = shb + i * 1024;
#pragma unroll
        for (int half = 0; half < 2; half++) {
            ulonglong2 wA0 = *(const ulonglong2*)(row + ((((2 * half + 0) * 2 + 0) ^ r) << 4));
            ulonglong2 wB0 = *(const ulonglong2*)(row + ((((2 * half + 0) * 2 + 1) ^ r) << 4));
            ulonglong2 wA1 = *(const ulonglong2*)(row + ((((2 * half + 1) * 2 + 0) ^ r) << 4));
            ulonglong2 wB1 = *(const ulonglong2*)(row + ((((2 * half + 1) * 2 + 1) ^ r) << 4));
#pragma unroll
            for (int j = 0; j < 4; j++) {
                unsigned long long xb;
                xb = bcast2(v[j].x);
                ffma2(acc[j][2 * half + 0], xb, wA0.x);
                ffma2(acc[j][2 * half + 1], xb, wA1.x);
                xb = bcast2(v[j].y);
                ffma2(acc[j][2 * half + 0], xb, wA0.y);
                ffma2(acc[j][2 * half + 1], xb, wA1.y);
                xb = bcast2(v[j].z);
                ffma2(acc[j][2 * half + 0], xb, wB0.x);
                ffma2(acc[j][2 * half + 1], xb, wB1.x);
                xb = bcast2(v[j].w);
                ffma2(acc[j][2 * half + 0], xb, wB0.y);
                ffma2(acc[j][2 * half + 1], xb, wB1.y);
            }
        }
    }

#pragma unroll
    for (int j = 0; j < 4; j++) {
        float s[8];
#pragma unroll
        for (int p = 0; p < 4; p++) unpack2(acc[j][p], s[2 * p], s[2 * p + 1]);
#pragma unroll
        for (int d = 1; d < 8; d <<= 1) {
#pragma unroll
            for (int o = 0; o < 8; o++)
                s[o] += __shfl_xor_sync(0xffffffffu, s[o], d);
        }
        int node = nbase + j;
        if (r == 0 && node < NN) {
            float4* tp = (float4*)(g_tmp + (size_t)node * 8);
            tp[0] = make_float4(s[0], s[1], s[2], s[3]);
            tp[1] = make_float4(s[4], s[5], s[6], s[7]);
        }
    }

    // fused zeroing of both agg buffers (1 float4 each per thread)
    int zi = blockIdx.x * 256 + tid;           // grid*256 = 200192 >= NN*2
    if (zi < NN * 2) {
        float4 z = make_float4(0.f, 0.f, 0.f, 0.f);
        ((float4*)g_aggA)[zi] = z;
        ((float4*)g_aggB)[zi] = z;
    }
}

// ---------------- edge pass 1: fused convert + scatter (tmp -> aggA) -------
__global__ void edgecv_k(const void* __restrict__ edge_index,
                         const float* __restrict__ w) {
    int e = blockIdx.x * blockDim.x + threadIdx.x;
    if (e >= NE) return;
    int s, d;
    if (g_is64) {
        const long long* p = (const long long*)edge_index;
        s = (int)__ldg(&p[e]); d = (int)__ldg(&p[NE + e]);
    } else {
        const int* p = (const int*)edge_index;
        s = __ldg(&p[e]); d = __ldg(&p[NE + e]);
    }
    g_edge[e] = make_int2(s, d);
    float wt = __ldg(&w[e]);
    const float4* ts = (const float4*)(g_tmp + (size_t)s * 8);
    float* ad = g_aggA + (size_t)d * 8;
    float4 a = __ldg(ts);
    float4 b = __ldg(ts + 1);
    red4(ad,     a.x * wt, a.y * wt, a.z * wt, a.w * wt);
    red4(ad + 4, b.x * wt, b.y * wt, b.z * wt, b.w * wt);
}

// ---------------- edge pass: plain (tmp -> aggA) ---------------------------
__global__ void edge_k(const float* __restrict__ w) {
    int e = blockIdx.x * blockDim.x + threadIdx.x;
    if (e >= NE) return;
    int2 sd = __ldg(&g_edge[e]);
    float wt = __ldg(&w[e]);
    const float4* ts = (const float4*)(g_tmp + (size_t)sd.x * 8);
    float* ad = g_aggA + (size_t)sd.y * 8;
    float4 a = __ldg(ts);
    float4 b = __ldg(ts + 1);
    red4(ad,     a.x * wt, a.y * wt, a.z * wt, a.w * wt);
    red4(ad + 4, b.x * wt, b.y * wt, b.z * wt, b.w * wt);
}

// ---------------- edge pass with fused relu: relu(aggA[src]+b)*w -> aggB ---
__global__ void edge_relu_k(const float* __restrict__ w,
                            const float* __restrict__ bias) {
    int e = blockIdx.x * blockDim.x + threadIdx.x;
    if (e >= NE) return;
    int2 sd = __ldg(&g_edge[e]);
    float wt = __ldg(&w[e]);
    const float4* ts = (const float4*)(g_aggA + (size_t)sd.x * 8);
    float* ad = g_aggB + (size_t)sd.y * 8;
    float4 a = __ldg(ts);
    float4 b = __ldg(ts + 1);
    float h0 = fmaxf(a.x + __ldg(&bias[0]), 0.f);
    float h1 = fmaxf(a.y + __ldg(&bias[1]), 0.f);
    float h2 = fmaxf(a.z + __ldg(&bias[2]), 0.f);
    float h3 = fmaxf(a.w + __ldg(&bias[3]), 0.f);
    float h4 = fmaxf(b.x + __ldg(&bias[4]), 0.f);
    float h5 = fmaxf(b.y + __ldg(&bias[5]), 0.f);
    float h6 = fmaxf(b.z + __ldg(&bias[6]), 0.f);
    float h7 = fmaxf(b.w + __ldg(&bias[7]), 0.f);
    red4(ad,     h0 * wt, h1 * wt, h2 * wt, h3 * wt);
    red4(ad + 4, h4 * wt, h5 * wt, h6 * wt, h7 * wt);
}

// ---------------- fused mid: tmp = relu(aggB@W2 + b2) @ W3; zero aggA,aggB -
__global__ void tmid(const float* __restrict__ W2, const float* __restrict__ b2,
                     const float* __restrict__ W3) {
    int n = blockIdx.x * blockDim.x + threadIdx.x;
    if (n >= NN) return;
    float4* brow = (float4*)(g_aggB + (size_t)n * 8);
    float4 v0 = brow[0], v1 = brow[1];
    float h[8] = {v0.x, v0.y, v0.z, v0.w, v1.x, v1.y, v1.z, v1.w};
    float4 z = make_float4(0.f, 0.f, 0.f, 0.f);
    brow[0] = z; brow[1] = z;
    float4* arow = (float4*)(g_aggA + (size_t)n * 8);
    arow[0] = z; arow[1] = z;

    float m[16];
#pragma unroll
    for (int o = 0; o < 16; o++) m[o] = __ldg(&b2[o]);
#pragma unroll
    for (int j = 0; j < 8; j++) {
        float hj = h[j];
#pragma unroll
        for (int o = 0; o < 16; o++)
            m[o] += hj * __ldg(&W2[j * 16 + o]);
    }
#pragma unroll
    for (int o = 0; o < 16; o++) m[o] = fmaxf(m[o], 0.f);

    float acc[8];
#pragma unroll
    for (int o = 0; o < 8; o++) acc[o] = 0.f;
#pragma unroll
    for (int j = 0; j < 16; j++) {
        float mj = m[j];
#pragma unroll
        for (int o = 0; o < 8; o++)
            acc[o] += mj * __ldg(&W3[j * 8 + o]);
    }
    float4* trow = (float4*)(g_tmp + (size_t)n * 8);
    trow[0] = make_float4(acc[0], acc[1], acc[2], acc[3]);
    trow[1] = make_float4(acc[4], acc[5], acc[6], acc[7]);
}

// ---------------- final: out = log_softmax(aggB@W4 + b4) -------------------
__global__ void lsm_kernel(const float* __restrict__ W4, const float* __restrict__ b4,
                           float* __restrict__ out) {
    int n = blockIdx.x * blockDim.x + threadIdx.x;
    if (n >= NN) return;
    const float4* brow = (const float4*)(g_aggB + (size_t)n * 8);
    float4 v0 = __ldg(brow), v1 = __ldg(brow + 1);
    float h[8] = {v0.x, v0.y, v0.z, v0.w, v1.x, v1.y, v1.z, v1.w};

    float v[10];
#pragma unroll
    for (int o = 0; o < 10; o++) v[o] = __ldg(&b4[o]);
#pragma unroll
    for (int j = 0; j < 8; j++) {
        float hj = h[j];
#pragma unroll
        for (int o = 0; o < 10; o++)
            v[o] += hj * __ldg(&W4[j * 10 + o]);
    }
    float m = -1e30f;
#pragma unroll
    for (int o = 0; o < 10; o++) m = fmaxf(m, v[o]);
    float s = 0.f;
#pragma unroll
    for (int o = 0; o < 10; o++) s += expf(v[o] - m);
    float l = logf(s);
#pragma unroll
    for (int o = 0; o < 10; o++) out[(size_t)n * 10 + o] = v[o] - m - l;
}

// ---------------- launch ---------------------------------------------------
extern "C" void kernel_launch(void* const* d_in, const int* in_sizes, int n_in,
                              void* d_out, int out_size) {
    const float* x  = (const float*)d_in[0];
    const void*  ei = d_in[1];
    const float* ew = (const float*)d_in[2];
    const float* W1 = (const float*)d_in[3];
    const float* b1 = (const float*)d_in[4];
    const float* W2 = (const float*)d_in[5];
    const float* b2 = (const float*)d_in[6];
    const float* W3 = (const float*)d_in[7];
    const float* b3 = (const float*)d_in[8];
    const float* W4 = (const float*)d_in[9];
    const float* b4 = (const float*)d_in[10];
    float* out = (float*)d_out;

    detect_kernel<<<1, 256>>>((const unsigned int*)ei);      // 0
    l1_kernel<<<(NN + 127) / 128, 256>>>(x, W1);             // 1: tmp = x@W1; aggA=aggB=0
    edgecv_k<<<EBLK, 256>>>(ei, ew);                         // 2: aggA = A@(xW1)
    edge_relu_k<<<EBLK, 256>>>(ew, b1);                      // 3: aggB = A@relu(aggA+b1)
    tmid<<<NBLK, 256>>>(W2, b2, W3);                         // 4: tmp; aggA=aggB=0
    edge_k<<<EBLK, 256>>>(ew);                               // 5: aggA = A@tmp
    edge_relu_k<<<EBLK, 256>>>(ew, b3);                      // 6: aggB = A@relu(aggA+b3)
    lsm_kernel<<<NBLK, 256>>>(W4, b4, out);                  // 7
}